// round 8
// baseline (speedup 1.0000x reference)
#include <cuda_runtime.h>

#define BATCH 4
#define CIN   256
#define DIM   64
#define HWDIM 64
#define NPIX  4096
#define LN_EPS 1e-5f

// ---------------- scratch (device globals; no allocation allowed) ----------
__device__ float g_att[BATCH * DIM * NPIX];   // inner projection out [b][d][n]
__device__ float g_q  [BATCH * DIM * NPIX];   // [b][d][n]
__device__ float g_k  [BATCH * DIM * NPIX];   // [b][d][n]
__device__ float g_vt [BATCH * NPIX * DIM];   // V transposed: [b][n][d]
__device__ float g_ao [BATCH * DIM * NPIX];   // attention out [b][d][n]
__device__ float g_wt [DIM * CIN];            // w_out transposed [d][c]

// ---------------- packed fp32x2 helpers (FFMA2: 2x fp32 FMA rate) ----------
typedef unsigned long long ull_t;

__device__ __forceinline__ ull_t pack2(float lo, float hi) {
    ull_t r; asm("mov.b64 %0, {%1, %2};" : "=l"(r) : "f"(lo), "f"(hi)); return r;
}
__device__ __forceinline__ void unpack2(ull_t v, float& lo, float& hi) {
    asm("mov.b64 {%0, %1}, %2;" : "=f"(lo), "=f"(hi) : "l"(v));
}
__device__ __forceinline__ ull_t ffma2(ull_t a, ull_t b, ull_t c) {
    ull_t d; asm("fma.rn.f32x2 %0, %1, %2, %3;" : "=l"(d) : "l"(a), "l"(b), "l"(c));
    return d;
}
__device__ __forceinline__ ull_t fmul2(ull_t a, ull_t b) {
    ull_t d; asm("mul.rn.f32x2 %0, %1, %2;" : "=l"(d) : "l"(a), "l"(b));
    return d;
}

// ============================================================================
// Kernel 0: transpose w_out [c][d] -> g_wt [d][c] (tiny; enables coalesced
// broadcast loads in k_out_ln without a 64-register weight array)
// ============================================================================
__global__ __launch_bounds__(256) void k_transpose_w(const float* __restrict__ w_out)
{
    const int d = blockIdx.x;
    const int c = threadIdx.x;
    g_wt[d * CIN + c] = w_out[c * DIM + d];
}

// ============================================================================
// Kernel 1: 1x1 in-projection  att[b,d,n] = sum_c w_in[d,c] * x[b,c,n] + b_in
// Tiled GEMM with f32x2 packed FMA. 4x4 microtile -> 4x(2x2) packed.
// ============================================================================
__global__ __launch_bounds__(256) void k_proj_in(
    const float* __restrict__ x, const float* __restrict__ w,
    const float* __restrict__ bias)
{
    __shared__ float ws[32 * 68];   // [ci][d]
    __shared__ float xs[32 * 68];   // [ci][p]
    const int b   = blockIdx.y;
    const int n0  = blockIdx.x * 64;
    const int tid = threadIdx.x;
    const int ti  = tid >> 4;       // d group 0..15
    const int tj  = tid & 15;       // pixel group 0..15

    ull_t acc2[4][2];
    #pragma unroll
    for (int i = 0; i < 4; i++) { acc2[i][0] = 0ull; acc2[i][1] = 0ull; }

    for (int c0 = 0; c0 < CIN; c0 += 32) {
        __syncthreads();
        #pragma unroll
        for (int t = 0; t < 8; t++) {
            int idx = tid + t * 256;
            int d = idx >> 5, ci = idx & 31;
            ws[ci * 68 + d] = w[d * CIN + c0 + ci];
        }
        #pragma unroll
        for (int t = 0; t < 2; t++) {
            int idx4 = tid + t * 256;
            int ci = idx4 >> 4, p4 = idx4 & 15;
            float4 v = *(const float4*)&x[((b * CIN) + c0 + ci) * NPIX + n0 + p4 * 4];
            *(float4*)&xs[ci * 68 + p4 * 4] = v;
        }
        __syncthreads();
        #pragma unroll 16
        for (int ci = 0; ci < 32; ci++) {
            float4 a4 = *(const float4*)&ws[ci * 68 + 4 * ti];
            ulonglong2 b2 = *(const ulonglong2*)&xs[ci * 68 + 4 * tj];
            ull_t d0 = pack2(a4.x, a4.x), d1 = pack2(a4.y, a4.y);
            ull_t d2 = pack2(a4.z, a4.z), d3 = pack2(a4.w, a4.w);
            acc2[0][0] = ffma2(d0, b2.x, acc2[0][0]);
            acc2[0][1] = ffma2(d0, b2.y, acc2[0][1]);
            acc2[1][0] = ffma2(d1, b2.x, acc2[1][0]);
            acc2[1][1] = ffma2(d1, b2.y, acc2[1][1]);
            acc2[2][0] = ffma2(d2, b2.x, acc2[2][0]);
            acc2[2][1] = ffma2(d2, b2.y, acc2[2][1]);
            acc2[3][0] = ffma2(d3, b2.x, acc2[3][0]);
            acc2[3][1] = ffma2(d3, b2.y, acc2[3][1]);
        }
    }
    #pragma unroll
    for (int di = 0; di < 4; di++) {
        int d = 4 * ti + di;
        float bb = bias[d];
        float f0, f1, f2, f3;
        unpack2(acc2[di][0], f0, f1);
        unpack2(acc2[di][1], f2, f3);
        float4 o = make_float4(f0 + bb, f1 + bb, f2 + bb, f3 + bb);
        *(float4*)&g_att[((b * DIM) + d) * NPIX + n0 + 4 * tj] = o;
    }
}

// ============================================================================
// Kernel 2: 3x3 conv (pad 1). blockIdx.z selects q/k/v. (unchanged)
// ============================================================================
__global__ __launch_bounds__(256) void k_qkv(
    const float* __restrict__ wq, const float* __restrict__ bq,
    const float* __restrict__ wk, const float* __restrict__ bk,
    const float* __restrict__ wv, const float* __restrict__ bv)
{
    __shared__ float att_s[DIM * 100];   // [c][10][10] halo tile
    __shared__ float ws[8 * 64 * 9];     // weight chunk: [ci][d][k]

    const int b = blockIdx.y;
    const int z = blockIdx.z;
    const float* w    = (z == 0) ? wq : (z == 1) ? wk : wv;
    const float* bias = (z == 0) ? bq : (z == 1) ? bk : bv;

    const int tile = blockIdx.x;
    const int th = (tile >> 3) * 8, tw = (tile & 7) * 8;
    const int tid = threadIdx.x;

    for (int idx = tid; idx < DIM * 100; idx += 256) {
        int c = idx / 100, rem = idx - c * 100;
        int r = rem / 10, cc = rem - r * 10;
        int gh = th - 1 + r, gw = tw - 1 + cc;
        float v = 0.f;
        if (gh >= 0 && gh < HWDIM && gw >= 0 && gw < HWDIM)
            v = g_att[((b * DIM) + c) * NPIX + gh * HWDIM + gw];
        att_s[idx] = v;
    }

    const int d  = tid & 63;
    const int sub = tid >> 6;
    const int sy = (sub >> 1) * 4, sx = (sub & 1) * 4;
    float acc[16] = {};

    for (int c8 = 0; c8 < 8; c8++) {
        __syncthreads();
        #pragma unroll
        for (int t = 0; t < 18; t++) {
            int idx = tid + t * 256;
            int ci = idx / 576, rem2 = idx - ci * 576;
            int dd = rem2 / 9, k = rem2 - dd * 9;
            ws[idx] = w[(dd * DIM + c8 * 8 + ci) * 9 + k];
        }
        __syncthreads();
        #pragma unroll
        for (int ci = 0; ci < 8; ci++) {
            int c = c8 * 8 + ci;
            float patch[36];
            #pragma unroll
            for (int ry = 0; ry < 6; ry++)
                #pragma unroll
                for (int rx = 0; rx < 6; rx++)
                    patch[ry * 6 + rx] = att_s[c * 100 + (sy + ry) * 10 + sx + rx];
            const float* wp = &ws[(ci * 64 + d) * 9];
            float w9[9];
            #pragma unroll
            for (int k = 0; k < 9; k++) w9[k] = wp[k];
            #pragma unroll
            for (int py = 0; py < 4; py++)
                #pragma unroll
                for (int px = 0; px < 4; px++) {
                    float a = acc[py * 4 + px];
                    #pragma unroll
                    for (int ky = 0; ky < 3; ky++)
                        #pragma unroll
                        for (int kx = 0; kx < 3; kx++)
                            a += w9[ky * 3 + kx] * patch[(py + ky) * 6 + px + kx];
                    acc[py * 4 + px] = a;
                }
        }
    }

    float bb = bias[d];
    if (z == 2) {
        #pragma unroll
        for (int py = 0; py < 4; py++)
            #pragma unroll
            for (int px = 0; px < 4; px++) {
                int n = (th + sy + py) * HWDIM + tw + sx + px;
                g_vt[(b * NPIX + n) * DIM + d] = acc[py * 4 + px] + bb;
            }
    } else {
        float* out = (z == 0) ? g_q : g_k;
        #pragma unroll
        for (int py = 0; py < 4; py++)
            #pragma unroll
            for (int px = 0; px < 4; px++) {
                int n = (th + sy + py) * HWDIM + tw + sx + px;
                out[((b * DIM) + d) * NPIX + n] = acc[py * 4 + px] + bb;
            }
    }
}

// ============================================================================
// Kernel 3: flash attention, fp32 via packed f32x2 FMA.
// BM=BN=64, head dim 64. 256 threads: ti=tid>>3 (32 query groups of 2 rows),
// tj=tid&7 (8 groups of 8 cols/channels). 2x8 microtile per thread.
// P stored bank-rotated: physical col = (j + 4*row) & 63 -> conflict-free
// broadcast reads in GEMM2.
// ============================================================================
__global__ __launch_bounds__(256) void k_flash()
{
    __shared__ float Qs [64 * 64];   // [c][i]
    __shared__ float KPs[64 * 64];   // phase A: K [c][j]; phase B: P (rotated)
    __shared__ float Vt [64 * 64];   // [j][c]

    const int b  = blockIdx.y;
    const int i0 = blockIdx.x * 64;
    const int tid = threadIdx.x;
    const int ti = tid >> 3;   // 0..31: rows 2ti, 2ti+1
    const int tj = tid & 7;    // 0..7:  cols/channels 8tj..8tj+7

    #pragma unroll
    for (int t = 0; t < 4; t++) {
        int idx4 = tid + t * 256;
        int c = idx4 >> 4, p4 = idx4 & 15;
        *(float4*)&Qs[c * 64 + p4 * 4] =
            *(const float4*)&g_q[((b * DIM) + c) * NPIX + i0 + p4 * 4];
    }

    ull_t o2[2][4];
    #pragma unroll
    for (int ii = 0; ii < 2; ii++)
        #pragma unroll
        for (int k = 0; k < 4; k++) o2[ii][k] = 0ull;
    float m[2] = {-1e30f, -1e30f}, l[2] = {0.f, 0.f};

    const int row0 = 2 * ti;           // this thread's two P rows
    const int roff0 = (4 * row0) & 63; // rotation offsets for P reads
    const int roff1 = (4 * row0 + 4) & 63;

    for (int jt = 0; jt < 64; jt++) {
        const int j0 = jt * 64;
        __syncthreads();   // previous GEMM2 reads of KPs/Vt done
        #pragma unroll
        for (int t = 0; t < 4; t++) {
            int idx4 = tid + t * 256;
            int r = idx4 >> 4, q4 = idx4 & 15;
            *(float4*)&KPs[r * 64 + q4 * 4] =
                *(const float4*)&g_k[((b * DIM) + r) * NPIX + j0 + q4 * 4];
            *(float4*)&Vt[r * 64 + q4 * 4] =
                *(const float4*)&g_vt[(b * NPIX + j0 + r) * DIM + q4 * 4];
        }
        __syncthreads();

        // ---- S = Q^T K (2 rows x 8 cols per thread, packed pairs) ----
        ull_t s2[2][4];
        #pragma unroll
        for (int ii = 0; ii < 2; ii++)
            #pragma unroll
            for (int k = 0; k < 4; k++) s2[ii][k] = 0ull;

        #pragma unroll 16
        for (int c = 0; c < 64; c++) {
            float a0 = Qs[c * 64 + row0];
            float a1 = Qs[c * 64 + row0 + 1];
            ull_t d0 = pack2(a0, a0);
            ull_t d1 = pack2(a1, a1);
            ulonglong2 bL = *(const ulonglong2*)&KPs[c * 64 + 8 * tj];
            ulonglong2 bH = *(const ulonglong2*)&KPs[c * 64 + 8 * tj + 4];
            s2[0][0] = ffma2(d0, bL.x, s2[0][0]);
            s2[0][1] = ffma2(d0, bL.y, s2[0][1]);
            s2[0][2] = ffma2(d0, bH.x, s2[0][2]);
            s2[0][3] = ffma2(d0, bH.y, s2[0][3]);
            s2[1][0] = ffma2(d1, bL.x, s2[1][0]);
            s2[1][1] = ffma2(d1, bL.y, s2[1][1]);
            s2[1][2] = ffma2(d1, bH.x, s2[1][2]);
            s2[1][3] = ffma2(d1, bH.y, s2[1][3]);
        }

        // ---- online softmax over this thread's 8 cols + 8-lane reduce ----
        float p[2][8];
        #pragma unroll
        for (int ii = 0; ii < 2; ii++) {
            float s[8];
            unpack2(s2[ii][0], s[0], s[1]);
            unpack2(s2[ii][1], s[2], s[3]);
            unpack2(s2[ii][2], s[4], s[5]);
            unpack2(s2[ii][3], s[6], s[7]);
            float mt = s[0];
            #pragma unroll
            for (int k = 1; k < 8; k++) mt = fmaxf(mt, s[k]);
            mt = fmaxf(mt, __shfl_xor_sync(0xffffffffu, mt, 4, 8));
            mt = fmaxf(mt, __shfl_xor_sync(0xffffffffu, mt, 2, 8));
            mt = fmaxf(mt, __shfl_xor_sync(0xffffffffu, mt, 1, 8));
            float mn = fmaxf(m[ii], mt);
            float sc = __expf(m[ii] - mn);
            float rs = 0.f;
            #pragma unroll
            for (int k = 0; k < 8; k++) {
                p[ii][k] = __expf(s[k] - mn);
                rs += p[ii][k];
            }
            rs += __shfl_xor_sync(0xffffffffu, rs, 4, 8);
            rs += __shfl_xor_sync(0xffffffffu, rs, 2, 8);
            rs += __shfl_xor_sync(0xffffffffu, rs, 1, 8);
            l[ii] = l[ii] * sc + rs;
            m[ii] = mn;
            ull_t sc2 = pack2(sc, sc);
            #pragma unroll
            for (int k = 0; k < 4; k++) o2[ii][k] = fmul2(o2[ii][k], sc2);
        }

        __syncthreads();   // all GEMM1 reads of K done before P overwrites
        #pragma unroll
        for (int ii = 0; ii < 2; ii++) {
            int r = row0 + ii;
            int c0 = (8 * tj + 4 * r) & 63;       // rotated, stays 4-aligned
            int c1 = (8 * tj + 4 + 4 * r) & 63;
            *(float4*)&KPs[r * 64 + c0] =
                make_float4(p[ii][0], p[ii][1], p[ii][2], p[ii][3]);
            *(float4*)&KPs[r * 64 + c1] =
                make_float4(p[ii][4], p[ii][5], p[ii][6], p[ii][7]);
        }
        __syncthreads();   // P visible

        // ---- O += P * V (channels 8tj..8tj+7 as 4 packed pairs) ----
        #pragma unroll 16
        for (int j = 0; j < 64; j++) {
            ulonglong2 vL = *(const ulonglong2*)&Vt[j * 64 + 8 * tj];
            ulonglong2 vH = *(const ulonglong2*)&Vt[j * 64 + 8 * tj + 4];
            float p0 = KPs[row0 * 64 + ((j + roff0) & 63)];
            float p1 = KPs[(row0 + 1) * 64 + ((j + roff1) & 63)];
            ull_t pp0 = pack2(p0, p0);
            ull_t pp1 = pack2(p1, p1);
            o2[0][0] = ffma2(pp0, vL.x, o2[0][0]);
            o2[0][1] = ffma2(pp0, vL.y, o2[0][1]);
            o2[0][2] = ffma2(pp0, vH.x, o2[0][2]);
            o2[0][3] = ffma2(pp0, vH.y, o2[0][3]);
            o2[1][0] = ffma2(pp1, vL.x, o2[1][0]);
            o2[1][1] = ffma2(pp1, vL.y, o2[1][1]);
            o2[1][2] = ffma2(pp1, vH.x, o2[1][2]);
            o2[1][3] = ffma2(pp1, vH.y, o2[1][3]);
        }
    }

    #pragma unroll
    for (int ii = 0; ii < 2; ii++) {
        float inv = 1.f / l[ii];
        int i = i0 + row0 + ii;
        #pragma unroll
        for (int k = 0; k < 4; k++) {
            float f0, f1;
            unpack2(o2[ii][k], f0, f1);
            g_ao[((b * DIM) + 8 * tj + 2 * k) * NPIX + i]     = f0 * inv;
            g_ao[((b * DIM) + 8 * tj + 2 * k + 1) * NPIX + i] = f1 * inv;
        }
    }
}

// ============================================================================
// Kernel 4: out = LayerNorm_c( gamma*x + (w_out @ ao + b_out) )
// block = 16 pixels, 256 threads (one per output channel).
// x / out staged through smem for coalesced global traffic; weights read from
// pre-transposed g_wt (coalesced broadcast); GEMM in packed f32x2.
// ============================================================================
__global__ __launch_bounds__(256) void k_out_ln(
    const float* __restrict__ x,
    const float* __restrict__ b_out, const float* __restrict__ gamma,
    const float* __restrict__ ln_w, const float* __restrict__ ln_b,
    float* __restrict__ out)
{
    __shared__ float aos[DIM * 16];    // [d][p]
    __shared__ float xs[CIN * 17];     // [c][p], padded stride 17
    __shared__ float red1[8 * 16];
    __shared__ float red2[8 * 16];
    __shared__ float mus[16], rstds[16];

    const int blk = blockIdx.x;
    const int b  = blk >> 8;            // 256 blocks per batch
    const int n0 = (blk & 255) * 16;
    const int c  = threadIdx.x;

    // stage ao tile [64 d][16 p]
    #pragma unroll
    for (int t = 0; t < 4; t++) {
        int idx = c + t * 256;
        int d = idx >> 4, p = idx & 15;
        aos[idx] = g_ao[((b * DIM) + d) * NPIX + n0 + p];
    }
    // stage x tile coalesced: 1024 float4 loads
    #pragma unroll
    for (int t = 0; t < 4; t++) {
        int idx4 = c + t * 256;
        int ch = idx4 >> 2, p4 = idx4 & 3;
        float4 v = *(const float4*)&x[((b * CIN) + ch) * NPIX + n0 + p4 * 4];
        xs[ch * 17 + p4 * 4 + 0] = v.x;
        xs[ch * 17 + p4 * 4 + 1] = v.y;
        xs[ch * 17 + p4 * 4 + 2] = v.z;
        xs[ch * 17 + p4 * 4 + 3] = v.w;
    }
    const float g0 = gamma[0];
    const float bo = b_out[c];
    __syncthreads();

    // GEMM: tv[p] = b_out[c] + sum_d wt[d][c] * aos[d][p]   (packed pairs)
    ull_t tv2[8];
    {
        ull_t bb2 = pack2(bo, bo);
        #pragma unroll
        for (int q = 0; q < 8; q++) tv2[q] = bb2;
    }
    #pragma unroll 16
    for (int d = 0; d < 64; d++) {
        float wd = __ldg(&g_wt[d * CIN + c]);
        ull_t wd2 = pack2(wd, wd);
        const ulonglong2* ar = (const ulonglong2*)&aos[d * 16];
        ulonglong2 a01 = ar[0], a23 = ar[1], a45 = ar[2], a67 = ar[3];
        tv2[0] = ffma2(wd2, a01.x, tv2[0]);
        tv2[1] = ffma2(wd2, a01.y, tv2[1]);
        tv2[2] = ffma2(wd2, a23.x, tv2[2]);
        tv2[3] = ffma2(wd2, a23.y, tv2[3]);
        tv2[4] = ffma2(wd2, a45.x, tv2[4]);
        tv2[5] = ffma2(wd2, a45.y, tv2[5]);
        tv2[6] = ffma2(wd2, a67.x, tv2[6]);
        tv2[7] = ffma2(wd2, a67.y, tv2[7]);
    }

    float tv[16];
    #pragma unroll
    for (int q = 0; q < 8; q++) unpack2(tv2[q], tv[2 * q], tv[2 * q + 1]);
    #pragma unroll
    for (int p = 0; p < 16; p++) tv[p] += g0 * xs[c * 17 + p];

    // LN statistics over 256 channels per pixel
    const int warp = c >> 5, lane = c & 31;
    #pragma unroll
    for (int p = 0; p < 16; p++) {
        float s1 = tv[p], s2 = tv[p] * tv[p];
        #pragma unroll
        for (int off = 16; off > 0; off >>= 1) {
            s1 += __shfl_xor_sync(0xffffffffu, s1, off);
            s2 += __shfl_xor_sync(0xffffffffu, s2, off);
        }
        if (lane == 0) { red1[warp * 16 + p] = s1; red2[warp * 16 + p] = s2; }
    }
    __syncthreads();
    if (c < 16) {
        float s1 = 0.f, s2 = 0.f;
        #pragma unroll
        for (int w = 0; w < 8; w++) { s1 += red1[w * 16 + c]; s2 += red2[w * 16 + c]; }
        float mu  = s1 * (1.f / 256.f);
        float var = s2 * (1.f / 256.f) - mu * mu;
        mus[c] = mu;
        rstds[c] = rsqrtf(var + LN_EPS);
    }
    __syncthreads();

    const float lw = ln_w[c], lb = ln_b[c];
    #pragma unroll
    for (int p = 0; p < 16; p++)
        xs[c * 17 + p] = (tv[p] - mus[p]) * rstds[p] * lw + lb;
    __syncthreads();

    // coalesced output stores
    #pragma unroll
    for (int t = 0; t < 4; t++) {
        int idx4 = c + t * 256;
        int ch = idx4 >> 2, p4 = idx4 & 3;
        float4 o4 = make_float4(xs[ch * 17 + p4 * 4 + 0],
                                xs[ch * 17 + p4 * 4 + 1],
                                xs[ch * 17 + p4 * 4 + 2],
                                xs[ch * 17 + p4 * 4 + 3]);
        *(float4*)&out[((b * CIN) + ch) * NPIX + n0 + p4 * 4] = o4;
    }
}

// ============================================================================
extern "C" void kernel_launch(void* const* d_in, const int* in_sizes, int n_in,
                              void* d_out, int out_size)
{
    const float* x     = (const float*)d_in[0];
    const float* w_in  = (const float*)d_in[1];
    const float* b_in  = (const float*)d_in[2];
    const float* wq    = (const float*)d_in[3];
    const float* bq    = (const float*)d_in[4];
    const float* wk    = (const float*)d_in[5];
    const float* bk    = (const float*)d_in[6];
    const float* wv    = (const float*)d_in[7];
    const float* bv    = (const float*)d_in[8];
    const float* w_out = (const float*)d_in[9];
    const float* b_out = (const float*)d_in[10];
    const float* gamma = (const float*)d_in[11];
    const float* ln_w  = (const float*)d_in[12];
    const float* ln_b  = (const float*)d_in[13];
    float* out = (float*)d_out;

    k_transpose_w<<<DIM, CIN>>>(w_out);
    k_proj_in<<<dim3(64, BATCH), 256>>>(x, w_in, b_in);
    k_qkv<<<dim3(64, BATCH, 3), 256>>>(wq, bq, wk, bk, wv, bv);
    k_flash<<<dim3(64, BATCH), 256>>>();
    k_out_ln<<<BATCH * 256, 256>>>(x, b_out, gamma, ln_w, ln_b, out);
}

// round 13
// speedup vs baseline: 3.8745x; 3.8745x over previous
#include <cuda_runtime.h>
#include <cuda_fp16.h>
#include <cstdint>

#define BATCH 4
#define CIN   256
#define DIM   64
#define HWDIM 64
#define NPIX  4096
#define LN_EPS 1e-5f

// ---------------- scratch (device globals; no allocation allowed) ----------
__device__ float g_att[BATCH * DIM * NPIX];   // inner projection out [b][d][n]
__device__ float g_ao [BATCH * DIM * NPIX];   // attention out [b][d][n]
__device__ float g_wt [DIM * CIN];            // w_out transposed [d][c]

// fp16 hi/lo staging, PRE-SWIZZLED (SW128-style) 8KB tiles (64x64 halfs):
// Q: tile it=n>>6, byte sw128((n&63)*128 + d*2)   [row][d]
// K: tile jt=n>>6, byte sw128((n&63)*128 + d*2)   [key][d]
// V: tile jt=n>>6, byte sw128(d*128 + (n&63)*2)   [d][key]
__device__ __align__(16) unsigned char g_qh8[BATCH * 64 * 8192];
__device__ __align__(16) unsigned char g_ql8[BATCH * 64 * 8192];
__device__ __align__(16) unsigned char g_kh8[BATCH * 64 * 8192];
__device__ __align__(16) unsigned char g_kl8[BATCH * 64 * 8192];
__device__ __align__(16) unsigned char g_vh8[BATCH * 64 * 8192];
__device__ __align__(16) unsigned char g_vl8[BATCH * 64 * 8192];

// ---------------- helpers --------------------------------------------------
__device__ __forceinline__ uint32_t smem_u32(const void* p) {
    uint32_t a;
    asm("{ .reg .u64 t; cvta.to.shared.u64 t, %1; cvt.u32.u64 %0, t; }"
        : "=r"(a) : "l"(p));
    return a;
}
__device__ __forceinline__ uint32_t sw128(uint32_t off) {
    return off ^ ((off >> 3) & 0x70);
}
__device__ __forceinline__ void ldsm4(uint32_t& r0, uint32_t& r1,
                                      uint32_t& r2, uint32_t& r3, uint32_t addr) {
    asm volatile("ldmatrix.sync.aligned.m8n8.x4.shared.b16 {%0,%1,%2,%3}, [%4];"
        : "=r"(r0), "=r"(r1), "=r"(r2), "=r"(r3) : "r"(addr));
}
__device__ __forceinline__ void mma16816(float* d, const uint32_t* a,
                                         uint32_t b0, uint32_t b1) {
    asm volatile(
        "mma.sync.aligned.m16n8k16.row.col.f32.f16.f16.f32 "
        "{%0,%1,%2,%3}, {%4,%5,%6,%7}, {%8,%9}, {%0,%1,%2,%3};"
        : "+f"(d[0]), "+f"(d[1]), "+f"(d[2]), "+f"(d[3])
        : "r"(a[0]), "r"(a[1]), "r"(a[2]), "r"(a[3]), "r"(b0), "r"(b1));
}
__device__ __forceinline__ uint32_t hpack(__half a, __half b) {
    return (uint32_t)__half_as_ushort(a) | ((uint32_t)__half_as_ushort(b) << 16);
}

// ============================================================================
// Kernel 0: transpose w_out [c][d] -> g_wt [d][c]
// ============================================================================
__global__ __launch_bounds__(256) void k_transpose_w(const float* __restrict__ w_out)
{
    g_wt[blockIdx.x * CIN + threadIdx.x] = w_out[threadIdx.x * DIM + blockIdx.x];
}

// ============================================================================
// Kernel 1: 1x1 in-projection (plain FFMA, proven)
// ============================================================================
__global__ __launch_bounds__(256) void k_proj_in(
    const float* __restrict__ x, const float* __restrict__ w,
    const float* __restrict__ bias)
{
    __shared__ float ws[32 * 68];
    __shared__ float xs[32 * 68];
    const int b   = blockIdx.y;
    const int n0  = blockIdx.x * 64;
    const int tid = threadIdx.x;
    const int ti  = tid >> 4;
    const int tj  = tid & 15;

    float acc[4][4] = {};
    for (int c0 = 0; c0 < CIN; c0 += 32) {
        __syncthreads();
        #pragma unroll
        for (int t = 0; t < 8; t++) {
            int idx = tid + t * 256;
            int d = idx >> 5, ci = idx & 31;
            ws[ci * 68 + d] = w[d * CIN + c0 + ci];
        }
        #pragma unroll
        for (int t = 0; t < 2; t++) {
            int idx4 = tid + t * 256;
            int ci = idx4 >> 4, p4 = idx4 & 15;
            float4 v = *(const float4*)&x[((b * CIN) + c0 + ci) * NPIX + n0 + p4 * 4];
            *(float4*)&xs[ci * 68 + p4 * 4] = v;
        }
        __syncthreads();
        #pragma unroll
        for (int ci = 0; ci < 32; ci++) {
            float4 a4 = *(const float4*)&ws[ci * 68 + 4 * ti];
            float4 b4 = *(const float4*)&xs[ci * 68 + 4 * tj];
            acc[0][0] += a4.x * b4.x; acc[0][1] += a4.x * b4.y;
            acc[0][2] += a4.x * b4.z; acc[0][3] += a4.x * b4.w;
            acc[1][0] += a4.y * b4.x; acc[1][1] += a4.y * b4.y;
            acc[1][2] += a4.y * b4.z; acc[1][3] += a4.y * b4.w;
            acc[2][0] += a4.z * b4.x; acc[2][1] += a4.z * b4.y;
            acc[2][2] += a4.z * b4.z; acc[2][3] += a4.z * b4.w;
            acc[3][0] += a4.w * b4.x; acc[3][1] += a4.w * b4.y;
            acc[3][2] += a4.w * b4.z; acc[3][3] += a4.w * b4.w;
        }
    }
    #pragma unroll
    for (int di = 0; di < 4; di++) {
        int d = 4 * ti + di;
        float bb = bias[d];
        float4 o = make_float4(acc[di][0] + bb, acc[di][1] + bb,
                               acc[di][2] + bb, acc[di][3] + bb);
        *(float4*)&g_att[((b * DIM) + d) * NPIX + n0 + 4 * tj] = o;
    }
}

// ============================================================================
// Kernel 2: 3x3 conv (pad 1) -> fp16 hi/lo pre-swizzled 64x64 tiles
// ============================================================================
__global__ __launch_bounds__(256) void k_qkv(
    const float* __restrict__ wq, const float* __restrict__ bq,
    const float* __restrict__ wk, const float* __restrict__ bk,
    const float* __restrict__ wv, const float* __restrict__ bv)
{
    __shared__ float att_s[DIM * 100];
    __shared__ float ws[8 * 64 * 9];

    const int b = blockIdx.y;
    const int z = blockIdx.z;
    const float* w    = (z == 0) ? wq : (z == 1) ? wk : wv;
    const float* bias = (z == 0) ? bq : (z == 1) ? bk : bv;

    const int tile = blockIdx.x;
    const int th = (tile >> 3) * 8, tw = (tile & 7) * 8;
    const int tid = threadIdx.x;

    for (int idx = tid; idx < DIM * 100; idx += 256) {
        int c = idx / 100, rem = idx - c * 100;
        int r = rem / 10, cc = rem - r * 10;
        int gh = th - 1 + r, gw = tw - 1 + cc;
        float v = 0.f;
        if (gh >= 0 && gh < HWDIM && gw >= 0 && gw < HWDIM)
            v = g_att[((b * DIM) + c) * NPIX + gh * HWDIM + gw];
        att_s[idx] = v;
    }

    const int d  = tid & 63;
    const int sub = tid >> 6;
    const int sy = (sub >> 1) * 4, sx = (sub & 1) * 4;
    float acc[16] = {};

    for (int c8 = 0; c8 < 8; c8++) {
        __syncthreads();
        #pragma unroll
        for (int t = 0; t < 18; t++) {
            int idx = tid + t * 256;
            int ci = idx / 576, rem2 = idx - ci * 576;
            int dd = rem2 / 9, k = rem2 - dd * 9;
            ws[idx] = w[(dd * DIM + c8 * 8 + ci) * 9 + k];
        }
        __syncthreads();
        #pragma unroll
        for (int ci = 0; ci < 8; ci++) {
            int c = c8 * 8 + ci;
            float patch[36];
            #pragma unroll
            for (int ry = 0; ry < 6; ry++)
                #pragma unroll
                for (int rx = 0; rx < 6; rx++)
                    patch[ry * 6 + rx] = att_s[c * 100 + (sy + ry) * 10 + sx + rx];
            const float* wp = &ws[(ci * 64 + d) * 9];
            float w9[9];
            #pragma unroll
            for (int k = 0; k < 9; k++) w9[k] = wp[k];
            #pragma unroll
            for (int py = 0; py < 4; py++)
                #pragma unroll
                for (int px = 0; px < 4; px++) {
                    float a = acc[py * 4 + px];
                    #pragma unroll
                    for (int ky = 0; ky < 3; ky++)
                        #pragma unroll
                        for (int kx = 0; kx < 3; kx++)
                            a += w9[ky * 3 + kx] * patch[(py + ky) * 6 + px + kx];
                    acc[py * 4 + px] = a;
                }
        }
    }

    const float bb = bias[d];
    #pragma unroll
    for (int py = 0; py < 4; py++)
        #pragma unroll
        for (int px = 0; px < 4; px++) {
            float val = acc[py * 4 + px] + bb;
            int n = (th + sy + py) * HWDIM + tw + sx + px;
            __half hi = __float2half_rn(val);
            __half lo = __float2half_rn(val - __half2float(hi));
            int t = n >> 6, r = n & 63;
            size_t tbase = ((size_t)(b * 64 + t)) * 8192;
            if (z == 0) {
                uint32_t off = sw128((uint32_t)(r * 128 + d * 2));
                *(__half*)(g_qh8 + tbase + off) = hi;
                *(__half*)(g_ql8 + tbase + off) = lo;
            } else if (z == 1) {
                uint32_t off = sw128((uint32_t)(r * 128 + d * 2));
                *(__half*)(g_kh8 + tbase + off) = hi;
                *(__half*)(g_kl8 + tbase + off) = lo;
            } else {
                uint32_t off = sw128((uint32_t)(d * 128 + r * 2));
                *(__half*)(g_vh8 + tbase + off) = hi;
                *(__half*)(g_vl8 + tbase + off) = lo;
            }
        }
}

// ============================================================================
// Kernel 3: flash attention via mma.sync (fp16 hi/lo, f32 accumulate).
// BM=BN=64, 4 warps (warp = 16 query rows). Q A-frags persistent in regs.
// S = qh*kh + ql*kh + qh*kl ; O += ph*vh + pl*vh + ph*vl (ll dropped).
// Softmax fully in registers (2 rows/thread, shfl over 4-lane row groups).
// ============================================================================
__global__ __launch_bounds__(128) void k_flash_mma()
{
    __shared__ __align__(128) __half QH[4096], QL[4096];
    __shared__ __align__(128) __half KH[4096], KL[4096];
    __shared__ __align__(128) __half VH[4096], VL[4096];

    const int tid = threadIdx.x;
    const int w   = tid >> 5;
    const int l   = tid & 31;
    const int b   = blockIdx.y;
    const int it  = blockIdx.x;

    // ---- load Q tile (hi/lo), 2 x 8KB ----
    {
        const float4* sh = (const float4*)(g_qh8 + ((size_t)(b * 64 + it)) * 8192);
        const float4* sl = (const float4*)(g_ql8 + ((size_t)(b * 64 + it)) * 8192);
        float4* dh = (float4*)QH;
        float4* dl = (float4*)QL;
        #pragma unroll
        for (int t = 0; t < 4; t++) {
            dh[tid + t * 128] = sh[tid + t * 128];
            dl[tid + t * 128] = sl[tid + t * 128];
        }
    }
    __syncthreads();

    // ---- persistent Q A-frags (4 k-chunks x hi/lo) ----
    uint32_t qh[4][4], ql[4][4];
    {
        const uint32_t qbH = smem_u32(QH), qbL = smem_u32(QL);
        int row  = 16 * w + (l & 15);
        int colb = (l >> 4) << 3;
        #pragma unroll
        for (int kc = 0; kc < 4; kc++) {
            uint32_t off = sw128((uint32_t)(row * 128 + (kc * 16 + colb) * 2));
            ldsm4(qh[kc][0], qh[kc][1], qh[kc][2], qh[kc][3], qbH + off);
            ldsm4(ql[kc][0], ql[kc][1], ql[kc][2], ql[kc][3], qbL + off);
        }
    }

    const uint32_t kbH = smem_u32(KH), kbL = smem_u32(KL);
    const uint32_t vbH = smem_u32(VH), vbL = smem_u32(VL);
    const int brow = ((l >> 4) << 3) + (l & 7);   // B-frag ldmatrix row within 16-grp
    const int bcol = (l & 8);                     // B-frag col offset (0/8)

    float O[8][4];
    #pragma unroll
    for (int t = 0; t < 8; t++)
        #pragma unroll
        for (int k = 0; k < 4; k++) O[t][k] = 0.f;
    float m0 = -1e30f, m1 = -1e30f, l0 = 0.f, l1 = 0.f;

    for (int jt = 0; jt < 64; jt++) {
        __syncthreads();
        {
            size_t gb = ((size_t)(b * 64 + jt)) * 8192;
            const float4* kh = (const float4*)(g_kh8 + gb);
            const float4* kl = (const float4*)(g_kl8 + gb);
            const float4* vh = (const float4*)(g_vh8 + gb);
            const float4* vl = (const float4*)(g_vl8 + gb);
            #pragma unroll
            for (int t = 0; t < 4; t++) {
                ((float4*)KH)[tid + t * 128] = kh[tid + t * 128];
                ((float4*)KL)[tid + t * 128] = kl[tid + t * 128];
                ((float4*)VH)[tid + t * 128] = vh[tid + t * 128];
                ((float4*)VL)[tid + t * 128] = vl[tid + t * 128];
            }
        }
        __syncthreads();

        // ---- S = Q^T K (16 x 64 per warp) ----
        float S[8][4];
        #pragma unroll
        for (int t = 0; t < 8; t++)
            #pragma unroll
            for (int k = 0; k < 4; k++) S[t][k] = 0.f;

        #pragma unroll
        for (int kc = 0; kc < 4; kc++) {
            #pragma unroll
            for (int jp = 0; jp < 4; jp++) {
                uint32_t off = sw128(
                    (uint32_t)((16 * jp + brow) * 128 + (kc * 16 + bcol) * 2));
                uint32_t k0, k1, k2, k3;
                ldsm4(k0, k1, k2, k3, kbH + off);
                mma16816(S[2 * jp],     qh[kc], k0, k1);
                mma16816(S[2 * jp + 1], qh[kc], k2, k3);
                mma16816(S[2 * jp],     ql[kc], k0, k1);
                mma16816(S[2 * jp + 1], ql[kc], k2, k3);
                ldsm4(k0, k1, k2, k3, kbL + off);
                mma16816(S[2 * jp],     qh[kc], k0, k1);
                mma16816(S[2 * jp + 1], qh[kc], k2, k3);
            }
        }

        // ---- online softmax (rows r = l>>2 and r+8) ----
        float mx0 = -1e30f, mx1 = -1e30f;
        #pragma unroll
        for (int t = 0; t < 8; t++) {
            mx0 = fmaxf(mx0, fmaxf(S[t][0], S[t][1]));
            mx1 = fmaxf(mx1, fmaxf(S[t][2], S[t][3]));
        }
        mx0 = fmaxf(mx0, __shfl_xor_sync(0xffffffffu, mx0, 1));
        mx0 = fmaxf(mx0, __shfl_xor_sync(0xffffffffu, mx0, 2));
        mx1 = fmaxf(mx1, __shfl_xor_sync(0xffffffffu, mx1, 1));
        mx1 = fmaxf(mx1, __shfl_xor_sync(0xffffffffu, mx1, 2));
        const float mn0 = fmaxf(m0, mx0);
        const float mn1 = fmaxf(m1, mx1);
        const float sc0 = __expf(m0 - mn0);
        const float sc1 = __expf(m1 - mn1);
        m0 = mn0; m1 = mn1;

        uint32_t pah[4][4], pal[4][4];
        float rs0 = 0.f, rs1 = 0.f;
        #pragma unroll
        for (int kc2 = 0; kc2 < 4; kc2++) {
            const int t0 = 2 * kc2, t1 = 2 * kc2 + 1;
            float p00 = __expf(S[t0][0] - mn0), p01 = __expf(S[t0][1] - mn0);
            float p02 = __expf(S[t0][2] - mn1), p03 = __expf(S[t0][3] - mn1);
            float p10 = __expf(S[t1][0] - mn0), p11 = __expf(S[t1][1] - mn0);
            float p12 = __expf(S[t1][2] - mn1), p13 = __expf(S[t1][3] - mn1);
            rs0 += (p00 + p01) + (p10 + p11);
            rs1 += (p02 + p03) + (p12 + p13);
            __half h;
            // a0: P[r][c,c+1] of tile t0 ; a1: P[r+8][..] t0 ; a2/a3: tile t1
            h = __float2half_rn(p00); float q00 = p00 - __half2float(h); __half h00 = h;
            h = __float2half_rn(p01); float q01 = p01 - __half2float(h); __half h01 = h;
            h = __float2half_rn(p02); float q02 = p02 - __half2float(h); __half h02 = h;
            h = __float2half_rn(p03); float q03 = p03 - __half2float(h); __half h03 = h;
            h = __float2half_rn(p10); float q10 = p10 - __half2float(h); __half h10 = h;
            h = __float2half_rn(p11); float q11 = p11 - __half2float(h); __half h11 = h;
            h = __float2half_rn(p12); float q12 = p12 - __half2float(h); __half h12 = h;
            h = __float2half_rn(p13); float q13 = p13 - __half2float(h); __half h13 = h;
            pah[kc2][0] = hpack(h00, h01);
            pah[kc2][1] = hpack(h02, h03);
            pah[kc2][2] = hpack(h10, h11);
            pah[kc2][3] = hpack(h12, h13);
            pal[kc2][0] = hpack(__float2half_rn(q00), __float2half_rn(q01));
            pal[kc2][1] = hpack(__float2half_rn(q02), __float2half_rn(q03));
            pal[kc2][2] = hpack(__float2half_rn(q10), __float2half_rn(q11));
            pal[kc2][3] = hpack(__float2half_rn(q12), __float2half_rn(q13));
        }
        rs0 += __shfl_xor_sync(0xffffffffu, rs0, 1);
        rs0 += __shfl_xor_sync(0xffffffffu, rs0, 2);
        rs1 += __shfl_xor_sync(0xffffffffu, rs1, 1);
        rs1 += __shfl_xor_sync(0xffffffffu, rs1, 2);
        l0 = l0 * sc0 + rs0;
        l1 = l1 * sc1 + rs1;

        #pragma unroll
        for (int t = 0; t < 8; t++) {
            O[t][0] *= sc0; O[t][1] *= sc0;
            O[t][2] *= sc1; O[t][3] *= sc1;
        }

        // ---- O += P * V ----
        #pragma unroll
        for (int kc2 = 0; kc2 < 4; kc2++) {
            #pragma unroll
            for (int dp = 0; dp < 4; dp++) {
                uint32_t off = sw128(
                    (uint32_t)((16 * dp + brow) * 128 + (kc2 * 16 + bcol) * 2));
                uint32_t v0, v1, v2, v3;
                ldsm4(v0, v1, v2, v3, vbH + off);
                mma16816(O[2 * dp],     pah[kc2], v0, v1);
                mma16816(O[2 * dp + 1], pah[kc2], v2, v3);
                mma16816(O[2 * dp],     pal[kc2], v0, v1);
                mma16816(O[2 * dp + 1], pal[kc2], v2, v3);
                ldsm4(v0, v1, v2, v3, vbL + off);
                mma16816(O[2 * dp],     pah[kc2], v0, v1);
                mma16816(O[2 * dp + 1], pah[kc2], v2, v3);
            }
        }
    }

    // ---- epilogue: normalize + store [b][d][n] ----
    const float inv0 = 1.f / l0;
    const float inv1 = 1.f / l1;
    const int r  = l >> 2;
    const int c0 = (l & 3) * 2;
    const int ng = it * 64 + 16 * w;
    #pragma unroll
    for (int t = 0; t < 8; t++) {
        int d = 8 * t + c0;
        g_ao[((size_t)(b * DIM + d))     * NPIX + ng + r]     = O[t][0] * inv0;
        g_ao[((size_t)(b * DIM + d + 1)) * NPIX + ng + r]     = O[t][1] * inv0;
        g_ao[((size_t)(b * DIM + d))     * NPIX + ng + r + 8] = O[t][2] * inv1;
        g_ao[((size_t)(b * DIM + d + 1)) * NPIX + ng + r + 8] = O[t][3] * inv1;
    }
}

// ============================================================================
// Kernel 4: out = LayerNorm_c( gamma*x + (w_out @ ao + b_out) )
// ============================================================================
__global__ __launch_bounds__(256) void k_out_ln(
    const float* __restrict__ x,
    const float* __restrict__ b_out, const float* __restrict__ gamma,
    const float* __restrict__ ln_w, const float* __restrict__ ln_b,
    float* __restrict__ out)
{
    __shared__ float aos[DIM * 16];
    __shared__ float xs[CIN * 17];
    __shared__ float red1[8 * 16];
    __shared__ float red2[8 * 16];
    __shared__ float mus[16], rstds[16];

    const int blk = blockIdx.x;
    const int b  = blk >> 8;
    const int n0 = (blk & 255) * 16;
    const int c  = threadIdx.x;

    #pragma unroll
    for (int t = 0; t < 4; t++) {
        int idx = c + t * 256;
        int d = idx >> 4, p = idx & 15;
        aos[idx] = g_ao[((b * DIM) + d) * NPIX + n0 + p];
    }
    #pragma unroll
    for (int t = 0; t < 4; t++) {
        int idx4 = c + t * 256;
        int ch = idx4 >> 2, p4 = idx4 & 3;
        float4 v = *(const float4*)&x[((b * CIN) + ch) * NPIX + n0 + p4 * 4];
        xs[ch * 17 + p4 * 4 + 0] = v.x;
        xs[ch * 17 + p4 * 4 + 1] = v.y;
        xs[ch * 17 + p4 * 4 + 2] = v.z;
        xs[ch * 17 + p4 * 4 + 3] = v.w;
    }
    const float g0 = gamma[0];
    const float bo = b_out[c];
    __syncthreads();

    float tv[16];
    #pragma unroll
    for (int p = 0; p < 16; p++) tv[p] = bo;
    #pragma unroll 16
    for (int d = 0; d < 64; d++) {
        float wd = __ldg(&g_wt[d * CIN + c]);
        #pragma unroll
        for (int p = 0; p < 16; p++) tv[p] += wd * aos[d * 16 + p];
    }
    #pragma unroll
    for (int p = 0; p < 16; p++) tv[p] += g0 * xs[c * 17 + p];

    const int warp = c >> 5, lane = c & 31;
    #pragma unroll
    for (int p = 0; p < 16; p++) {
        float s1 = tv[p], s2 = tv[p] * tv[p];
        #pragma unroll
        for (int off = 16; off > 0; off >>= 1) {
            s1 += __shfl_xor_sync(0xffffffffu, s1, off);
            s2 += __shfl_xor_sync(0xffffffffu, s2, off);
        }
        if (lane == 0) { red1[warp * 16 + p] = s1; red2[warp * 16 + p] = s2; }
    }
    __syncthreads();
    if (c < 16) {
        float s1 = 0.f, s2 = 0.f;
        #pragma unroll
        for (int w = 0; w < 8; w++) { s1 += red1[w * 16 + c]; s2 += red2[w * 16 + c]; }
        float mu  = s1 * (1.f / 256.f);
        float var = s2 * (1.f / 256.f) - mu * mu;
        mus[c] = mu;
        rstds[c] = rsqrtf(var + LN_EPS);
    }
    __syncthreads();

    const float lw = ln_w[c], lb = ln_b[c];
    #pragma unroll
    for (int p = 0; p < 16; p++)
        xs[c * 17 + p] = (tv[p] - mus[p]) * rstds[p] * lw + lb;
    __syncthreads();

    #pragma unroll
    for (int t = 0; t < 4; t++) {
        int idx4 = c + t * 256;
        int ch = idx4 >> 2, p4 = idx4 & 3;
        float4 o4 = make_float4(xs[ch * 17 + p4 * 4 + 0],
                                xs[ch * 17 + p4 * 4 + 1],
                                xs[ch * 17 + p4 * 4 + 2],
                                xs[ch * 17 + p4 * 4 + 3]);
        *(float4*)&out[((b * CIN) + ch) * NPIX + n0 + p4 * 4] = o4;
    }
}

// ============================================================================
extern "C" void kernel_launch(void* const* d_in, const int* in_sizes, int n_in,
                              void* d_out, int out_size)
{
    const float* x     = (const float*)d_in[0];
    const float* w_in  = (const float*)d_in[1];
    const float* b_in  = (const float*)d_in[2];
    const float* wq    = (const float*)d_in[3];
    const float* bq    = (const float*)d_in[4];
    const float* wk    = (const float*)d_in[5];
    const float* bk    = (const float*)d_in[6];
    const float* wv    = (const float*)d_in[7];
    const float* bv    = (const float*)d_in[8];
    const float* w_out = (const float*)d_in[9];
    const float* b_out = (const float*)d_in[10];
    const float* gamma = (const float*)d_in[11];
    const float* ln_w  = (const float*)d_in[12];
    const float* ln_b  = (const float*)d_in[13];
    float* out = (float*)d_out;

    k_transpose_w<<<DIM, CIN>>>(w_out);
    k_proj_in<<<dim3(64, BATCH), 256>>>(x, w_in, b_in);
    k_qkv<<<dim3(64, BATCH, 3), 256>>>(wq, bq, wk, bk, wv, bv);
    k_flash_mma<<<dim3(64, BATCH), 128>>>();
    k_out_ln<<<BATCH * 256, 256>>>(x, b_out, gamma, ln_w, ln_b, out);
}